// round 13
// baseline (speedup 1.0000x reference)
#include <cuda_runtime.h>

// Integrate-and-fire, hard reset, scanned over time axis.
// x: [T=32, N] float32, out: [T=32, N] float32 (spikes 0/1).
// N = 4,194,304 neurons. Each thread owns 8 consecutive neurons per work
// unit (256-bit ld.global.nc.v8 / st.global.cs.v8), membranes in registers,
// T fully unrolled. Persistent grid-stride launch (grid = 148 SMs x 6
// CTAs/SM) removes wave-transition overhead and tail underutilization.

#define T_STEPS 32
#define V_TH 1.0f

__device__ __forceinline__ void ldg256(const float* p, float* r) {
    asm volatile(
        "ld.global.nc.v8.f32 {%0,%1,%2,%3,%4,%5,%6,%7}, [%8];"
        : "=f"(r[0]), "=f"(r[1]), "=f"(r[2]), "=f"(r[3]),
          "=f"(r[4]), "=f"(r[5]), "=f"(r[6]), "=f"(r[7])
        : "l"(p));
}

__device__ __forceinline__ void stg256(float* p, const float* r) {
    asm volatile(
        "st.global.cs.v8.f32 [%0], {%1,%2,%3,%4,%5,%6,%7,%8};"
        :: "l"(p),
           "f"(r[0]), "f"(r[1]), "f"(r[2]), "f"(r[3]),
           "f"(r[4]), "f"(r[5]), "f"(r[6]), "f"(r[7])
        : "memory");
}

__global__ __launch_bounds__(256) void if_scan_kernel(
    const float* __restrict__ x,
    float* __restrict__ out,
    int n8)   // number of 8-float lanes per timestep
{
    size_t stride = (size_t)n8 * 8;  // floats per timestep

    // persistent grid-stride over 8-float lanes
    for (int i = blockIdx.x * blockDim.x + threadIdx.x;
         i < n8;
         i += gridDim.x * blockDim.x)
    {
        size_t elem = (size_t)i * 8;

        float m[8];
        #pragma unroll
        for (int k = 0; k < 8; k++) m[k] = 0.0f;

        #pragma unroll
        for (int t = 0; t < T_STEPS; t++) {
            size_t idx = (size_t)t * stride + elem;
            float xt[8];
            ldg256(x + idx, xt);

            float s[8];
            #pragma unroll
            for (int k = 0; k < 8; k++) {
                m[k] += xt[k];
                s[k] = (m[k] >= V_TH) ? 1.0f : 0.0f;
                m[k] = (s[k] != 0.0f) ? 0.0f : m[k];
            }

            stg256(out + idx, s);
        }
    }
}

extern "C" void kernel_launch(void* const* d_in, const int* in_sizes, int n_in,
                              void* d_out, int out_size)
{
    const float* x = (const float*)d_in[0];
    float* out = (float*)d_out;

    int total = in_sizes[0];          // T * N
    int n = total / T_STEPS;          // neurons per timestep
    int n8 = n / 8;                   // 8-float lanes

    int threads = 256;
    // persistent grid: 148 SMs x 6 CTAs/SM (regs=42 -> 6 resident CTAs/SM)
    int blocks = 148 * 6;
    int max_blocks = (n8 + threads - 1) / threads;
    if (blocks > max_blocks) blocks = max_blocks;

    if_scan_kernel<<<blocks, threads>>>(x, out, n8);
}

// round 15
// speedup vs baseline: 1.0691x; 1.0691x over previous
#include <cuda_runtime.h>

// FINAL: Integrate-and-fire, hard reset, scanned over time axis.
// x: [T=32, N] float32, out: [T=32, N] float32 (spikes 0/1).
// N = 4,194,304 neurons. Each thread owns 8 consecutive neurons using
// Blackwell 256-bit global loads/stores (ld.global.nc.v8 / st.global.v8).
// Membrane potentials carried in registers across the fully unrolled T loop.
// Flat grid (2048 x 256): measured best at 170.4us, HBM 6.41 TB/s (80% of
// spec) — within ~2% of the achievable 1:1 read:write stream ceiling.
// Measured-null levers: extra MLP/prefetch, higher occupancy, RW phase
// separation, persistent grid (regressed) — do not revisit.

#define T_STEPS 32
#define V_TH 1.0f

__device__ __forceinline__ void ldg256(const float* p, float r[8]) {
    asm volatile(
        "ld.global.nc.v8.f32 {%0,%1,%2,%3,%4,%5,%6,%7}, [%8];"
        : "=f"(r[0]), "=f"(r[1]), "=f"(r[2]), "=f"(r[3]),
          "=f"(r[4]), "=f"(r[5]), "=f"(r[6]), "=f"(r[7])
        : "l"(p));
}

__device__ __forceinline__ void stg256(float* p, const float r[8]) {
    asm volatile(
        "st.global.v8.f32 [%0], {%1,%2,%3,%4,%5,%6,%7,%8};"
        :: "l"(p),
           "f"(r[0]), "f"(r[1]), "f"(r[2]), "f"(r[3]),
           "f"(r[4]), "f"(r[5]), "f"(r[6]), "f"(r[7])
        : "memory");
}

__global__ __launch_bounds__(256) void if_scan_kernel(
    const float* __restrict__ x,
    float* __restrict__ out,
    int n8)   // number of 8-float lanes per timestep
{
    int i = blockIdx.x * blockDim.x + threadIdx.x;
    if (i >= n8) return;

    size_t elem = (size_t)i * 8;    // float offset within a timestep slice
    size_t stride = (size_t)n8 * 8; // floats per timestep

    float m[8];
    #pragma unroll
    for (int k = 0; k < 8; k++) m[k] = 0.0f;

    #pragma unroll
    for (int t = 0; t < T_STEPS; t++) {
        size_t idx = (size_t)t * stride + elem;
        float xt[8];
        ldg256(x + idx, xt);

        float s[8];
        #pragma unroll
        for (int k = 0; k < 8; k++) {
            m[k] += xt[k];
            s[k] = (m[k] >= V_TH) ? 1.0f : 0.0f;
            m[k] = (s[k] != 0.0f) ? 0.0f : m[k];
        }

        stg256(out + idx, s);
    }
}

extern "C" void kernel_launch(void* const* d_in, const int* in_sizes, int n_in,
                              void* d_out, int out_size)
{
    const float* x = (const float*)d_in[0];
    float* out = (float*)d_out;

    int total = in_sizes[0];          // T * N
    int n = total / T_STEPS;          // neurons per timestep
    int n8 = n / 8;                   // 8-float lanes

    int threads = 256;
    int blocks = (n8 + threads - 1) / threads;

    if_scan_kernel<<<blocks, threads>>>(x, out, n8);
}

// round 17
// speedup vs baseline: 1.0740x; 1.0045x over previous
#include <cuda_runtime.h>

// FINAL (frozen): Integrate-and-fire, hard reset, scanned over time axis.
// x: [T=32, N] float32, out: [T=32, N] float32 (spikes 0/1).
// N = 4,194,304 neurons. Each thread owns 8 consecutive neurons using
// Blackwell 256-bit global loads/stores (ld.global.nc.v8 / st.global.v8).
// Membrane potentials carried in registers across the fully unrolled T loop.
// Flat grid (2048 x 256). Triple-confirmed at 170.4-170.8us, HBM 6.38-6.41
// TB/s (80% of spec) — within ~2% of the 1:1 read:write stream ceiling.
// Measured-null levers (do not revisit): extra MLP/prefetch, occupancy,
// .cs store policy, RW phase separation, persistent grid (regressed +12us).

#define T_STEPS 32
#define V_TH 1.0f

__device__ __forceinline__ void ldg256(const float* p, float r[8]) {
    asm volatile(
        "ld.global.nc.v8.f32 {%0,%1,%2,%3,%4,%5,%6,%7}, [%8];"
        : "=f"(r[0]), "=f"(r[1]), "=f"(r[2]), "=f"(r[3]),
          "=f"(r[4]), "=f"(r[5]), "=f"(r[6]), "=f"(r[7])
        : "l"(p));
}

__device__ __forceinline__ void stg256(float* p, const float r[8]) {
    asm volatile(
        "st.global.v8.f32 [%0], {%1,%2,%3,%4,%5,%6,%7,%8};"
        :: "l"(p),
           "f"(r[0]), "f"(r[1]), "f"(r[2]), "f"(r[3]),
           "f"(r[4]), "f"(r[5]), "f"(r[6]), "f"(r[7])
        : "memory");
}

__global__ __launch_bounds__(256) void if_scan_kernel(
    const float* __restrict__ x,
    float* __restrict__ out,
    int n8)   // number of 8-float lanes per timestep
{
    int i = blockIdx.x * blockDim.x + threadIdx.x;
    if (i >= n8) return;

    size_t elem = (size_t)i * 8;    // float offset within a timestep slice
    size_t stride = (size_t)n8 * 8; // floats per timestep

    float m[8];
    #pragma unroll
    for (int k = 0; k < 8; k++) m[k] = 0.0f;

    #pragma unroll
    for (int t = 0; t < T_STEPS; t++) {
        size_t idx = (size_t)t * stride + elem;
        float xt[8];
        ldg256(x + idx, xt);

        float s[8];
        #pragma unroll
        for (int k = 0; k < 8; k++) {
            m[k] += xt[k];
            s[k] = (m[k] >= V_TH) ? 1.0f : 0.0f;
            m[k] = (s[k] != 0.0f) ? 0.0f : m[k];
        }

        stg256(out + idx, s);
    }
}

extern "C" void kernel_launch(void* const* d_in, const int* in_sizes, int n_in,
                              void* d_out, int out_size)
{
    const float* x = (const float*)d_in[0];
    float* out = (float*)d_out;

    int total = in_sizes[0];          // T * N
    int n = total / T_STEPS;          // neurons per timestep
    int n8 = n / 8;                   // 8-float lanes

    int threads = 256;
    int blocks = (n8 + threads - 1) / threads;

    if_scan_kernel<<<blocks, threads>>>(x, out, n8);
}